// round 12
// baseline (speedup 1.0000x reference)
#include <cuda_runtime.h>
#include <math.h>

#define BATCH 2048
#define TSTEPS 100
#define NC 8
#define NH 64
#define NHID 128
#define NO 10
#define MT 14
#define NCTA 147
#define NTHR 512

#define KP1 68
#define KP2 132

#define OFF_WIN   0
#define OFF_WH    (OFF_WIN + 128*KP1)
#define OFF_BIN   (OFF_WH + 2*128*KP2)
#define OFF_BH    (OFF_BIN + 128)
#define OFF_BOUT  (OFF_BH + 256)
#define OFF_TIMES (OFF_BOUT + 512)
#define OFF_ZB    (OFF_TIMES + 104)
#define OFF_ZT    (OFF_ZB + MT*NH)
#define OFF_KA    (OFF_ZT + MT*NH)
#define OFF_HA    (OFF_KA + MT*NH)
#define OFF_HB    (OFF_HA + MT*NHID)
#define OFF_DX    (OFF_HB + MT*NHID)
#define OFF_LG    (OFF_DX + MT*NC)
#define SMEM_FLOATS (OFF_LG + 160)
#define SMEM_BYTES  (SMEM_FLOATS*4)

__device__ float g_nll[BATCH];
__device__ float g_corr[BATCH];

typedef unsigned long long ull;

__device__ __forceinline__ void fma2(ull &d, ull a, ull b){
    asm("fma.rn.f32x2 %0, %1, %2, %0;" : "+l"(d) : "l"(a), "l"(b));
}
__device__ __forceinline__ ull dup2(float x){
    ull r; asm("mov.b64 %0, {%1, %1};" : "=l"(r) : "f"(x)); return r;
}
__device__ __forceinline__ ull pk2(float x, float y){
    ull r; asm("mov.b64 %0, {%1, %2};" : "=l"(r) : "f"(x), "f"(y)); return r;
}
__device__ __forceinline__ float2 up2(ull v){
    float2 r; asm("mov.b64 {%0, %1}, %2;" : "=f"(r.x), "=f"(r.y) : "l"(v)); return r;
}
__device__ __forceinline__ ulonglong2 ld2(const float* p){
    return *reinterpret_cast<const ulonglong2*>(p);
}

// tanh(x) = sign(x)*(1 - 2/(exp2(2x/ln2)+1)); matches fp32 tanh to ~1e-7.
__device__ __forceinline__ float tanh_fast(float x){
    float ax = fabsf(x);
    float e;
    asm("ex2.approx.f32 %0, %1;" : "=f"(e) : "f"(ax * 2.8853900817779268f));
    float r;
    asm("rcp.approx.f32 %0, %1;" : "=f"(r) : "f"(e + 1.0f));
    float t = fmaf(-2.0f, r, 1.0f);
    return copysignf(t, x);
}

// out[R rows][128] = relu(in @ W + b). 512 threads: c = tid&127 (one col),
// 4 row-groups. WT[col][k] in SMEM, stride KP (132/68: 4-bank lane step ->
// conflict-free LDS.128 within quarter-warp phases). a-loads group-uniform
// -> broadcast.
template<int R, int K, int KP>
__device__ __forceinline__ void dense_relu(const float* __restrict__ sin,
        const float* __restrict__ WT, const float* __restrict__ bias,
        float* __restrict__ sout, int r0, int tid)
{
    const int c = tid & 127;
    ull acc[R];
    #pragma unroll
    for (int r=0;r<R;r++) acc[r]=0ull;
    const float* wp = WT + c*KP;
    const float* ap = sin + r0*K;
    #pragma unroll
    for (int k=0;k<K;k+=4){
        ulonglong2 w = ld2(wp + k);
        #pragma unroll
        for (int r=0;r<R;r++){
            ulonglong2 a = ld2(ap + r*K + k);
            fma2(acc[r], a.x, w.x); fma2(acc[r], a.y, w.y);
        }
    }
    const float b = bias[c];
    #pragma unroll
    for (int r=0;r<R;r++){
        float2 u = up2(acc[r]);
        sout[(r0+r)*NHID + c] = fmaxf(u.x + u.y + b, 0.f);
    }
}

// Layer 4 + fused RK4 update. 16 warps = 2 row-groups (7 rows) x 8 j-chunks
// (64 floats). Lane owns j-pair jq = ch*64 + 2l; per k ONE lane-contiguous
// LDG.64 (256B/warp -> 2 wavefronts; total 4096 wf/eval, 2x dedup as R11).
// kb+=8 keeps 8 LDGs in flight; 4 warps/SMSP hide the 234-cyc L2 latency.
// dx contraction closes with xor-1 + xor-2 butterfly; l%4==0 lanes update
// h = ch*8 + l/4.
__device__ __forceinline__ void layer_out_update(const float* __restrict__ h3,
        const float* __restrict__ Wout, const float* __restrict__ bout,
        const float* __restrict__ dx, float* __restrict__ zb_s,
        float* __restrict__ zt_s, float* __restrict__ ka_s,
        int tid, int st, float dtv)
{
    const int l  = tid & 31;
    const int w  = tid >> 5;
    const int rg = w >> 3;            // 0 or 1
    const int ch = w & 7;             // j-chunk of 64 floats
    const int r0 = rg * 7;
    const int jq = (ch << 6) + (l << 1);
    ull acc[7];
    {
        ull b = pk2(bout[jq], bout[jq+1]);
        #pragma unroll
        for (int r=0;r<7;r++) acc[r]=b;
    }
    const float* wp = Wout + jq;
    #pragma unroll 1
    for (int kb=0; kb<NHID; kb+=8){
        ull wv[8];
        #pragma unroll
        for (int kk=0;kk<8;kk++)
            wv[kk] = *reinterpret_cast<const ull*>(wp + (size_t)(kb+kk)*(NH*NC));
        float4 hv[7];
        #pragma unroll
        for (int r=0;r<7;r++)
            hv[r] = *reinterpret_cast<const float4*>(&h3[(r0+r)*NHID + kb]);
        #pragma unroll
        for (int kk=0;kk<4;kk++){
            #pragma unroll
            for (int r=0;r<7;r++){
                float a;
                if      (kk==0) a = hv[r].x;
                else if (kk==1) a = hv[r].y;
                else if (kk==2) a = hv[r].z;
                else            a = hv[r].w;
                fma2(acc[r], dup2(a), wv[kk]);
            }
        }
        #pragma unroll
        for (int r=0;r<7;r++)
            hv[r] = *reinterpret_cast<const float4*>(&h3[(r0+r)*NHID + kb + 4]);
        #pragma unroll
        for (int kk=0;kk<4;kk++){
            #pragma unroll
            for (int r=0;r<7;r++){
                float a;
                if      (kk==0) a = hv[r].x;
                else if (kk==1) a = hv[r].y;
                else if (kk==2) a = hv[r].z;
                else            a = hv[r].w;
                fma2(acc[r], dup2(a), wv[kk+4]);
            }
        }
    }
    const int c0 = (l & 3) << 1;              // c-pair within h block
    const int h  = (ch << 3) + (l >> 2);
    #pragma unroll
    for (int r=0;r<7;r++){
        float2 dv = *reinterpret_cast<const float2*>(dx + (r0+r)*NC + c0);
        float2 u = up2(acc[r]);
        float pg = tanh_fast(u.x)*dv.x + tanh_fast(u.y)*dv.y;
        pg += __shfl_xor_sync(0xffffffffu, pg, 1);
        pg += __shfl_xor_sync(0xffffffffu, pg, 2);
        if ((l & 3) == 0){
            const int   idx = (r0+r)*NH + h;
            const float zb  = zb_s[idx];
            if (st==0){
                ka_s[idx] = pg;
                zt_s[idx] = fmaf(0.5f*dtv, pg, zb);
            } else if (st==1){
                ka_s[idx] = fmaf(2.f, pg, ka_s[idx]);
                zt_s[idx] = fmaf(0.5f*dtv, pg, zb);
            } else if (st==2){
                ka_s[idx] = fmaf(2.f, pg, ka_s[idx]);
                zt_s[idx] = fmaf(dtv, pg, zb);
            } else {
                float zn = fmaf(dtv*(1.0f/6.0f), ka_s[idx] + pg, zb);
                zb_s[idx] = zn; zt_s[idx] = zn;
            }
        }
    }
}

__global__ void __launch_bounds__(NTHR, 1)
cde_kernel(const float* __restrict__ coeffs, const int* __restrict__ y,
           const float* __restrict__ times,
           const float* __restrict__ W_init, const float* __restrict__ b_init,
           const float* __restrict__ W_in,   const float* __restrict__ b_in,
           const float* __restrict__ W_h,    const float* __restrict__ b_h,
           const float* __restrict__ W_out,  const float* __restrict__ b_out,
           const float* __restrict__ W_read, const float* __restrict__ b_read)
{
    extern __shared__ float sm[];
    const int tid  = threadIdx.x;
    const int row0 = blockIdx.x * MT;
    // Dense row-groups {4,4,3,3} over 128-thread groups.
    const int grp = tid >> 7;
    const int r0d = (grp < 2) ? (grp << 2) : (8 + (grp - 2) * 3);

    for (int idx=tid; idx<NH*NHID; idx+=NTHR){
        int k=idx>>7, c=idx&127; sm[OFF_WIN + c*KP1 + k] = W_in[idx];
    }
    for (int idx=tid; idx<2*NHID*NHID; idx+=NTHR){
        int l=idx>>14, rem=idx&16383, k=rem>>7, c=rem&127;
        sm[OFF_WH + l*(128*KP2) + c*KP2 + k] = W_h[idx];
    }
    for (int idx=tid; idx<NHID;   idx+=NTHR) sm[OFF_BIN+idx]  = b_in[idx];
    for (int idx=tid; idx<2*NHID; idx+=NTHR) sm[OFF_BH+idx]   = b_h[idx];
    for (int idx=tid; idx<NH*NC;  idx+=NTHR) sm[OFF_BOUT+idx] = b_out[idx];
    for (int idx=tid; idx<TSTEPS; idx+=NTHR) sm[OFF_TIMES+idx]= times[idx];

    for (int idx=tid; idx<MT*NH; idx+=NTHR){
        int r = idx/NH, hh = idx%NH;
        int row = row0 + r;
        float a = b_init[hh];
        if (row < BATCH){
            const float* crow = coeffs + (size_t)row*(TSTEPS*NC);
            #pragma unroll
            for (int c=0;c<NC;c++) a += crow[c]*W_init[c*NH+hh];
        }
        sm[OFF_ZB+idx]=a; sm[OFF_ZT+idx]=a;
    }
    __syncthreads();

    #pragma unroll 1
    for (int i=0;i<TSTEPS-1;i++){
        const float dtv = sm[OFF_TIMES+i+1]-sm[OFF_TIMES+i];
        if (tid < MT*NC){
            int r = tid >> 3, c = tid & 7;
            int row = row0 + r;
            float d = 0.f;
            if (row < BATCH){
                size_t base = (size_t)row*(TSTEPS*NC) + (size_t)i*NC + c;
                d = (coeffs[base+NC]-coeffs[base]) / dtv;
            }
            sm[OFF_DX+tid] = d;
        }
        #pragma unroll 1
        for (int st=0; st<4; st++){
            if (grp < 2) dense_relu<4,NH,KP1>(sm+OFF_ZT, sm+OFF_WIN, sm+OFF_BIN, sm+OFF_HA, r0d, tid);
            else         dense_relu<3,NH,KP1>(sm+OFF_ZT, sm+OFF_WIN, sm+OFF_BIN, sm+OFF_HA, r0d, tid);
            __syncthreads();
            if (grp < 2) dense_relu<4,NHID,KP2>(sm+OFF_HA, sm+OFF_WH, sm+OFF_BH, sm+OFF_HB, r0d, tid);
            else         dense_relu<3,NHID,KP2>(sm+OFF_HA, sm+OFF_WH, sm+OFF_BH, sm+OFF_HB, r0d, tid);
            __syncthreads();
            if (grp < 2) dense_relu<4,NHID,KP2>(sm+OFF_HB, sm+OFF_WH+128*KP2, sm+OFF_BH+128, sm+OFF_HA, r0d, tid);
            else         dense_relu<3,NHID,KP2>(sm+OFF_HB, sm+OFF_WH+128*KP2, sm+OFF_BH+128, sm+OFF_HA, r0d, tid);
            __syncthreads();
            layer_out_update(sm+OFF_HA, W_out, sm+OFF_BOUT, sm+OFF_DX,
                             sm+OFF_ZB, sm+OFF_ZT, sm+OFF_KA, tid, st, dtv);
            __syncthreads();
        }
    }

    if (tid < MT*NO){
        int r = tid/NO, o = tid%NO;
        float a = b_read[o];
        const float* zr = sm + OFF_ZB + r*NH;
        #pragma unroll
        for (int hh=0; hh<NH; hh++) a += zr[hh]*W_read[hh*NO+o];
        sm[OFF_LG + r*NO + o] = a;
    }
    __syncthreads();
    if (tid < MT && (row0 + tid) < BATCH){
        const float* lg = sm + OFF_LG + tid*NO;
        float m = lg[0]; int am = 0;
        #pragma unroll
        for (int o=1;o<NO;o++){ if (lg[o] > m){ m = lg[o]; am = o; } }
        float se = 0.f;
        #pragma unroll
        for (int o=0;o<NO;o++) se += expf(lg[o]-m);
        float lse = m + logf(se);
        int row = row0 + tid;
        int yr = y[row];
        g_nll[row]  = lse - lg[yr];
        g_corr[row] = (am==yr) ? 1.f : 0.f;
    }
}

__global__ void reduce_kernel(float* __restrict__ out, int out_size){
    __shared__ float s1[256], s2[256];
    int tid = threadIdx.x;
    float a=0.f, b=0.f;
    for (int i=tid; i<BATCH; i+=256){ a += g_nll[i]; b += g_corr[i]; }
    s1[tid]=a; s2[tid]=b; __syncthreads();
    for (int s=128; s>0; s>>=1){
        if (tid<s){ s1[tid]+=s1[tid+s]; s2[tid]+=s2[tid+s]; }
        __syncthreads();
    }
    if (tid==0){
        out[0] = s1[0] / (float)BATCH;
        if (out_size>1) out[1] = s2[0];
    }
}

// 3 noops before cde: cde_kernel lands at process launch #6 = ncu -s 5 -c 1.
__global__ void noop_kernel(){}

extern "C" void kernel_launch(void* const* d_in, const int* in_sizes, int n_in,
                              void* d_out, int out_size)
{
    const float* coeffs = (const float*)d_in[0];
    const int*   y      = (const int*)  d_in[1];
    const float* times  = (const float*)d_in[2];
    const float* W_init = (const float*)d_in[3];
    const float* b_init = (const float*)d_in[4];
    const float* W_in   = (const float*)d_in[5];
    const float* b_in   = (const float*)d_in[6];
    const float* W_h    = (const float*)d_in[7];
    const float* b_h    = (const float*)d_in[8];
    const float* W_out  = (const float*)d_in[9];
    const float* b_out  = (const float*)d_in[10];
    const float* W_read = (const float*)d_in[11];
    const float* b_read = (const float*)d_in[12];
    float* out = (float*)d_out;

    cudaFuncSetAttribute(cde_kernel, cudaFuncAttributeMaxDynamicSharedMemorySize, SMEM_BYTES);

    noop_kernel<<<1, 32>>>();
    noop_kernel<<<1, 32>>>();
    noop_kernel<<<1, 32>>>();
    cde_kernel<<<NCTA, NTHR, SMEM_BYTES>>>(coeffs, y, times, W_init, b_init,
                                           W_in, b_in, W_h, b_h, W_out, b_out,
                                           W_read, b_read);
    reduce_kernel<<<1, 256>>>(out, out_size);
}

// round 13
// speedup vs baseline: 1.1273x; 1.1273x over previous
#include <cuda_runtime.h>
#include <math.h>

#define BATCH 2048
#define TSTEPS 100
#define NC 8
#define NH 64
#define NHID 128
#define NO 10
#define MT 14
#define NCTA 147
#define NTHR 512

#define KP1 68
#define KP2 132

#define OFF_WIN   0
#define OFF_WH    (OFF_WIN + 128*KP1)
#define OFF_BIN   (OFF_WH + 2*128*KP2)
#define OFF_BH    (OFF_BIN + 128)
#define OFF_BOUT  (OFF_BH + 256)
#define OFF_TIMES (OFF_BOUT + 512)
#define OFF_ZB    (OFF_TIMES + 104)
#define OFF_ZT    (OFF_ZB + MT*NH)
#define OFF_KA    (OFF_ZT + MT*NH)
#define OFF_HA    (OFF_KA + MT*NH)
#define OFF_HB    (OFF_HA + MT*NHID)
#define OFF_DX    (OFF_HB + MT*NHID)
#define OFF_LG    (OFF_DX + MT*NC)
#define OFF_PT    (OFF_LG + 160)          // partial-sum staging: 14*512 floats
#define SMEM_FLOATS (OFF_PT + MT*512)
#define SMEM_BYTES  (SMEM_FLOATS*4)       // ~223.5 KB

__device__ float g_nll[BATCH];
__device__ float g_corr[BATCH];

typedef unsigned long long ull;

__device__ __forceinline__ void fma2(ull &d, ull a, ull b){
    asm("fma.rn.f32x2 %0, %1, %2, %0;" : "+l"(d) : "l"(a), "l"(b));
}
__device__ __forceinline__ ull add2(ull a, ull b){
    ull r; asm("add.rn.f32x2 %0, %1, %2;" : "=l"(r) : "l"(a), "l"(b)); return r;
}
__device__ __forceinline__ ull dup2(float x){
    ull r; asm("mov.b64 %0, {%1, %1};" : "=l"(r) : "f"(x)); return r;
}
__device__ __forceinline__ ull pk2(float x, float y){
    ull r; asm("mov.b64 %0, {%1, %2};" : "=l"(r) : "f"(x), "f"(y)); return r;
}
__device__ __forceinline__ float2 up2(ull v){
    float2 r; asm("mov.b64 {%0, %1}, %2;" : "=f"(r.x), "=f"(r.y) : "l"(v)); return r;
}
__device__ __forceinline__ ulonglong2 ld2(const float* p){
    return *reinterpret_cast<const ulonglong2*>(p);
}

// tanh(x) = sign(x)*(1 - 2/(exp2(2x/ln2)+1)); matches fp32 tanh to ~1e-7.
__device__ __forceinline__ float tanh_fast(float x){
    float ax = fabsf(x);
    float e;
    asm("ex2.approx.f32 %0, %1;" : "=f"(e) : "f"(ax * 2.8853900817779268f));
    float r;
    asm("rcp.approx.f32 %0, %1;" : "=f"(r) : "f"(e + 1.0f));
    float t = fmaf(-2.0f, r, 1.0f);
    return copysignf(t, x);
}

// out[14][128] = relu(in[14][K] @ W + b), K-SPLIT across warp pairs.
// 512 threads = 2 row-groups (7 rows) x 2 k-halves x 128 cols.
// kh=1 stores packed partial to ptd; after sync kh=0 adds, collapses, relu.
template<int K, int KP>
__device__ __forceinline__ void dense_relu(const float* __restrict__ sin,
        const float* __restrict__ WT, const float* __restrict__ bias,
        float* __restrict__ sout, ull* __restrict__ ptd,
        int r0, int kh, int c)
{
    ull acc[7];
    #pragma unroll
    for (int r=0;r<7;r++) acc[r]=0ull;
    const float* wp = WT + c*KP + kh*(K/2);
    const float* ap = sin + r0*K + kh*(K/2);
    #pragma unroll
    for (int k=0;k<K/2;k+=4){
        ulonglong2 w = ld2(wp + k);
        #pragma unroll
        for (int r=0;r<7;r++){
            ulonglong2 a = ld2(ap + r*K + k);   // warp-uniform -> broadcast
            fma2(acc[r], a.x, w.x); fma2(acc[r], a.y, w.y);
        }
    }
    if (kh){
        #pragma unroll
        for (int r=0;r<7;r++) ptd[(r0+r)*128 + c] = acc[r];
    }
    __syncthreads();
    if (!kh){
        const float b = bias[c];
        #pragma unroll
        for (int r=0;r<7;r++){
            ull s = add2(acc[r], ptd[(r0+r)*128 + c]);
            float2 u = up2(s);
            sout[(r0+r)*NHID + c] = fmaxf(u.x + u.y + b, 0.f);
        }
    }
}

// Layer 4 + fused RK4, K-SPLIT. 16 warps = 2 row-groups x 2 k-halves x
// 4 j-chunks. Lane owns j-quad; per k one lane-contiguous LDG.128 (4 wf;
// totals identical to R11: LDG 4096 wf, hv 1792 wf). kh=1 stages packed
// partials in pt; kh=0 combines, tanh+dx contraction (shfl_xor(1)), and
// even lanes apply the RK4 stage update.
__device__ __forceinline__ void layer_out_update(const float* __restrict__ h3,
        const float* __restrict__ Wout, const float* __restrict__ bout,
        const float* __restrict__ dx, float* __restrict__ zb_s,
        float* __restrict__ zt_s, float* __restrict__ ka_s,
        float* __restrict__ pt, int tid, int st, float dtv)
{
    const int l  = tid & 31;
    const int w  = tid >> 5;
    const int rg = w >> 3;            // 0 or 1
    const int kh = (w >> 2) & 1;      // k-half
    const int ch = w & 3;             // j-chunk (128 floats)
    const int r0 = rg * 7;
    const int jq = (ch << 7) + (l << 2);
    ull acc[7][2];
    if (!kh){
        ull b0 = pk2(bout[jq],   bout[jq+1]);
        ull b1 = pk2(bout[jq+2], bout[jq+3]);
        #pragma unroll
        for (int r=0;r<7;r++){ acc[r][0]=b0; acc[r][1]=b1; }
    } else {
        #pragma unroll
        for (int r=0;r<7;r++){ acc[r][0]=0ull; acc[r][1]=0ull; }
    }
    const float* wp = Wout + jq;
    const int kbase = kh << 6;        // 0 or 64
    #pragma unroll 1
    for (int kb=0; kb<64; kb+=8){
        ulonglong2 wv[8];
        #pragma unroll
        for (int kk=0;kk<8;kk++)
            wv[kk] = ld2(wp + (size_t)(kbase+kb+kk)*(NH*NC));
        float4 hv0[7], hv1[7];
        #pragma unroll
        for (int r=0;r<7;r++){
            hv0[r] = *reinterpret_cast<const float4*>(&h3[(r0+r)*NHID + kbase + kb]);
            hv1[r] = *reinterpret_cast<const float4*>(&h3[(r0+r)*NHID + kbase + kb + 4]);
        }
        #pragma unroll
        for (int kk=0;kk<8;kk++){
            #pragma unroll
            for (int r=0;r<7;r++){
                float a;
                if      (kk==0) a = hv0[r].x;
                else if (kk==1) a = hv0[r].y;
                else if (kk==2) a = hv0[r].z;
                else if (kk==3) a = hv0[r].w;
                else if (kk==4) a = hv1[r].x;
                else if (kk==5) a = hv1[r].y;
                else if (kk==6) a = hv1[r].z;
                else            a = hv1[r].w;
                ull a2 = dup2(a);
                fma2(acc[r][0], a2, wv[kk].x);
                fma2(acc[r][1], a2, wv[kk].y);
            }
        }
    }
    if (kh){
        #pragma unroll
        for (int r=0;r<7;r++){
            ulonglong2 v; v.x = acc[r][0]; v.y = acc[r][1];
            *reinterpret_cast<ulonglong2*>(pt + (r0+r)*512 + jq) = v;
        }
    }
    __syncthreads();
    if (!kh){
        const int coff = (l & 1) << 2;
        const int h    = (ch << 4) + (l >> 1);
        #pragma unroll
        for (int r=0;r<7;r++){
            ulonglong2 p = *reinterpret_cast<const ulonglong2*>(pt + (r0+r)*512 + jq);
            ull s0 = add2(acc[r][0], p.x);
            ull s1 = add2(acc[r][1], p.y);
            float4 dv = *reinterpret_cast<const float4*>(dx + (r0+r)*NC + coff);
            float2 u;
            float pg;
            u = up2(s0); pg  = tanh_fast(u.x)*dv.x; pg += tanh_fast(u.y)*dv.y;
            u = up2(s1); pg += tanh_fast(u.x)*dv.z; pg += tanh_fast(u.y)*dv.w;
            pg += __shfl_xor_sync(0xffffffffu, pg, 1);
            if ((l & 1) == 0){
                const int   idx = (r0+r)*NH + h;
                const float zb  = zb_s[idx];
                if (st==0){
                    ka_s[idx] = pg;
                    zt_s[idx] = fmaf(0.5f*dtv, pg, zb);
                } else if (st==1){
                    ka_s[idx] = fmaf(2.f, pg, ka_s[idx]);
                    zt_s[idx] = fmaf(0.5f*dtv, pg, zb);
                } else if (st==2){
                    ka_s[idx] = fmaf(2.f, pg, ka_s[idx]);
                    zt_s[idx] = fmaf(dtv, pg, zb);
                } else {
                    float zn = fmaf(dtv*(1.0f/6.0f), ka_s[idx] + pg, zb);
                    zb_s[idx] = zn; zt_s[idx] = zn;
                }
            }
        }
    }
}

__global__ void __launch_bounds__(NTHR, 1)
cde_kernel(const float* __restrict__ coeffs, const int* __restrict__ y,
           const float* __restrict__ times,
           const float* __restrict__ W_init, const float* __restrict__ b_init,
           const float* __restrict__ W_in,   const float* __restrict__ b_in,
           const float* __restrict__ W_h,    const float* __restrict__ b_h,
           const float* __restrict__ W_out,  const float* __restrict__ b_out,
           const float* __restrict__ W_read, const float* __restrict__ b_read)
{
    extern __shared__ float sm[];
    const int tid  = threadIdx.x;
    const int row0 = blockIdx.x * MT;
    // Dense decomposition: rg = row-group (7 rows), kh = k-half, c = column.
    const int rgd = tid >> 8;
    const int khd = (tid >> 7) & 1;
    const int cd  = tid & 127;
    const int r0d = rgd * 7;
    ull* ptd = reinterpret_cast<ull*>(sm + OFF_PT);

    for (int idx=tid; idx<NH*NHID; idx+=NTHR){
        int k=idx>>7, c=idx&127; sm[OFF_WIN + c*KP1 + k] = W_in[idx];
    }
    for (int idx=tid; idx<2*NHID*NHID; idx+=NTHR){
        int l=idx>>14, rem=idx&16383, k=rem>>7, c=rem&127;
        sm[OFF_WH + l*(128*KP2) + c*KP2 + k] = W_h[idx];
    }
    for (int idx=tid; idx<NHID;   idx+=NTHR) sm[OFF_BIN+idx]  = b_in[idx];
    for (int idx=tid; idx<2*NHID; idx+=NTHR) sm[OFF_BH+idx]   = b_h[idx];
    for (int idx=tid; idx<NH*NC;  idx+=NTHR) sm[OFF_BOUT+idx] = b_out[idx];
    for (int idx=tid; idx<TSTEPS; idx+=NTHR) sm[OFF_TIMES+idx]= times[idx];

    for (int idx=tid; idx<MT*NH; idx+=NTHR){
        int r = idx/NH, hh = idx%NH;
        int row = row0 + r;
        float a = b_init[hh];
        if (row < BATCH){
            const float* crow = coeffs + (size_t)row*(TSTEPS*NC);
            #pragma unroll
            for (int c=0;c<NC;c++) a += crow[c]*W_init[c*NH+hh];
        }
        sm[OFF_ZB+idx]=a; sm[OFF_ZT+idx]=a;
    }
    __syncthreads();

    #pragma unroll 1
    for (int i=0;i<TSTEPS-1;i++){
        const float dtv = sm[OFF_TIMES+i+1]-sm[OFF_TIMES+i];
        if (tid < MT*NC){
            int r = tid >> 3, c = tid & 7;
            int row = row0 + r;
            float d = 0.f;
            if (row < BATCH){
                size_t base = (size_t)row*(TSTEPS*NC) + (size_t)i*NC + c;
                d = (coeffs[base+NC]-coeffs[base]) / dtv;
            }
            sm[OFF_DX+tid] = d;
        }
        #pragma unroll 1
        for (int st=0; st<4; st++){
            dense_relu<NH,KP1>(sm+OFF_ZT, sm+OFF_WIN, sm+OFF_BIN,
                               sm+OFF_HA, ptd, r0d, khd, cd);
            __syncthreads();
            dense_relu<NHID,KP2>(sm+OFF_HA, sm+OFF_WH, sm+OFF_BH,
                                 sm+OFF_HB, ptd, r0d, khd, cd);
            __syncthreads();
            dense_relu<NHID,KP2>(sm+OFF_HB, sm+OFF_WH+128*KP2, sm+OFF_BH+128,
                                 sm+OFF_HA, ptd, r0d, khd, cd);
            __syncthreads();
            layer_out_update(sm+OFF_HA, W_out, sm+OFF_BOUT, sm+OFF_DX,
                             sm+OFF_ZB, sm+OFF_ZT, sm+OFF_KA, sm+OFF_PT,
                             tid, st, dtv);
            __syncthreads();
        }
    }

    if (tid < MT*NO){
        int r = tid/NO, o = tid%NO;
        float a = b_read[o];
        const float* zr = sm + OFF_ZB + r*NH;
        #pragma unroll
        for (int hh=0; hh<NH; hh++) a += zr[hh]*W_read[hh*NO+o];
        sm[OFF_LG + r*NO + o] = a;
    }
    __syncthreads();
    if (tid < MT && (row0 + tid) < BATCH){
        const float* lg = sm + OFF_LG + tid*NO;
        float m = lg[0]; int am = 0;
        #pragma unroll
        for (int o=1;o<NO;o++){ if (lg[o] > m){ m = lg[o]; am = o; } }
        float se = 0.f;
        #pragma unroll
        for (int o=0;o<NO;o++) se += expf(lg[o]-m);
        float lse = m + logf(se);
        int row = row0 + tid;
        int yr = y[row];
        g_nll[row]  = lse - lg[yr];
        g_corr[row] = (am==yr) ? 1.f : 0.f;
    }
}

__global__ void reduce_kernel(float* __restrict__ out, int out_size){
    __shared__ float s1[256], s2[256];
    int tid = threadIdx.x;
    float a=0.f, b=0.f;
    for (int i=tid; i<BATCH; i+=256){ a += g_nll[i]; b += g_corr[i]; }
    s1[tid]=a; s2[tid]=b; __syncthreads();
    for (int s=128; s>0; s>>=1){
        if (tid<s){ s1[tid]+=s1[tid+s]; s2[tid]+=s2[tid+s]; }
        __syncthreads();
    }
    if (tid==0){
        out[0] = s1[0] / (float)BATCH;
        if (out_size>1) out[1] = s2[0];
    }
}

// 3 noops before cde: cde_kernel lands at process launch #6 = ncu -s 5 -c 1.
__global__ void noop_kernel(){}

extern "C" void kernel_launch(void* const* d_in, const int* in_sizes, int n_in,
                              void* d_out, int out_size)
{
    const float* coeffs = (const float*)d_in[0];
    const int*   y      = (const int*)  d_in[1];
    const float* times  = (const float*)d_in[2];
    const float* W_init = (const float*)d_in[3];
    const float* b_init = (const float*)d_in[4];
    const float* W_in   = (const float*)d_in[5];
    const float* b_in   = (const float*)d_in[6];
    const float* W_h    = (const float*)d_in[7];
    const float* b_h    = (const float*)d_in[8];
    const float* W_out  = (const float*)d_in[9];
    const float* b_out  = (const float*)d_in[10];
    const float* W_read = (const float*)d_in[11];
    const float* b_read = (const float*)d_in[12];
    float* out = (float*)d_out;

    cudaFuncSetAttribute(cde_kernel, cudaFuncAttributeMaxDynamicSharedMemorySize, SMEM_BYTES);

    noop_kernel<<<1, 32>>>();
    noop_kernel<<<1, 32>>>();
    noop_kernel<<<1, 32>>>();
    cde_kernel<<<NCTA, NTHR, SMEM_BYTES>>>(coeffs, y, times, W_init, b_init,
                                           W_in, b_in, W_h, b_h, W_out, b_out,
                                           W_read, b_read);
    reduce_kernel<<<1, 256>>>(out, out_size);
}